// round 15
// baseline (speedup 1.0000x reference)
#include <cuda_runtime.h>
#include <cstdint>
#include <math.h>

#define BMAX   4
#define NN     4096
#define DDIM   1024
#define MSPLIT 128
#define MCHUNK (NN / MSPLIT)     // 32
#define EPSV   1e-6f
#define BATCH  8

// Scratch (device globals: no allocation allowed)
__device__ float g_part[BMAX][MSPLIT][3][DDIM]; // partial H0/Hc/Hs (6 MB)
__device__ float g_csp[BMAX][MSPLIT][2];        // partial sum cos / sum sin
__device__ float g_H[BMAX][3][DDIM];            // reduced H0/Hc/Hs
__device__ float g_CS[BMAX][2];                 // final sum cos, sum sin

// Grid-barrier state (zero-initialized; self-resetting across graph replays)
__device__ unsigned int g_bar_cnt[2];
__device__ unsigned int g_bar_epoch[2];

__device__ __forceinline__ void grid_barrier(int id, unsigned int nb) {
    __syncthreads();
    if (threadIdx.x == 0) {
        __threadfence();                                  // publish this block's writes
        unsigned int e = atomicAdd(&g_bar_epoch[id], 0u); // atomic read (pre-arrival)
        if (atomicAdd(&g_bar_cnt[id], 1u) == nb - 1u) {
            g_bar_cnt[id] = 0u;                           // reset for next replay
            __threadfence();
            atomicAdd(&g_bar_epoch[id], 1u);              // release
        } else {
            while (atomicAdd(&g_bar_epoch[id], 0u) == e) __nanosleep(64);
        }
    }
    __syncthreads();
}

// ---------------------------------------------------------------------------
// Fused persistent kernel. grid = (MSPLIT, B) = 512 blocks, 256 threads.
// Residency: regs<=64 (launch_bounds), smem ~4.5KB -> 4 blocks/SM, 592 >= 512.
// ---------------------------------------------------------------------------
__global__ void __launch_bounds__(256, 4)
kernel_fused(const float* __restrict__ hidden,
             const float* __restrict__ phases,
             const float* __restrict__ alpha_p,
             float* __restrict__ out) {
    __shared__ float smc[MCHUNK], sms[MCHUNK], scf[MCHUNK];
    __shared__ float4 sred[4][64];
    const int b  = blockIdx.y;
    const int ms = blockIdx.x;
    const int m0 = ms * MCHUNK;
    const int t  = threadIdx.x;
    const unsigned int nb = gridDim.x * gridDim.y;

    // ---- trig for this block's 32 rows (used by phase A weights AND phase C)
    if (t < MCHUNK) {
        float p = phases[b * NN + m0 + t];
        float s, c;
        sincosf(p, &s, &c);
        smc[t] = c;
        sms[t] = s;
        float rc = c, rs = s;
#pragma unroll
        for (int off = 16; off > 0; off >>= 1) {
            rc += __shfl_xor_sync(0xffffffffu, rc, off);
            rs += __shfl_xor_sync(0xffffffffu, rs, off);
        }
        if (t == 0) { g_csp[b][ms][0] = rc; g_csp[b][ms][1] = rs; }
    }
    __syncthreads();

    // ================= Phase A: partial H0/Hc/Hs (reg-batched, MLP=8) ======
    const float4* hp = (const float4*)(hidden + ((size_t)b * NN + m0) * DDIM) + t;
    {
        float4 a0 = make_float4(0.f, 0.f, 0.f, 0.f);
        float4 ac = a0, as = a0;
        float4 buf[BATCH];
#pragma unroll
        for (int mm = 0; mm < MCHUNK; mm += BATCH) {
#pragma unroll
            for (int i = 0; i < BATCH; ++i)
                buf[i] = hp[(size_t)(mm + i) * (DDIM / 4)];
#pragma unroll
            for (int i = 0; i < BATCH; ++i) {
                float4 h = buf[i];
                float c = smc[mm + i], s = sms[mm + i];
                a0.x += h.x;               a0.y += h.y;
                a0.z += h.z;               a0.w += h.w;
                ac.x = fmaf(c, h.x, ac.x); ac.y = fmaf(c, h.y, ac.y);
                ac.z = fmaf(c, h.z, ac.z); ac.w = fmaf(c, h.w, ac.w);
                as.x = fmaf(s, h.x, as.x); as.y = fmaf(s, h.y, as.y);
                as.z = fmaf(s, h.z, as.z); as.w = fmaf(s, h.w, as.w);
            }
        }
        ((float4*)g_part[b][ms][0])[t] = a0;
        ((float4*)g_part[b][ms][1])[t] = ac;
        ((float4*)g_part[b][ms][2])[t] = as;
    }

    grid_barrier(0, nb);

    // ================= Phase B: blocks ms<12 fold partials -> g_H ==========
    if (ms < 12) {
        const int comp = ms >> 2;                 // 0..2
        const int q    = ms & 3;                  // d-quarter
        const int col  = q * 64 + (t & 63);
        const int fs   = t >> 6;                  // 0..3 fold slice

        if (ms == 0 && t < 64) {
            int which = t >> 5;
            int lane  = t & 31;
            float v = 0.f;
#pragma unroll
            for (int i = 0; i < MSPLIT / 32; ++i)
                v += __ldcg(&g_csp[b][lane + i * 32][which]);
#pragma unroll
            for (int off = 16; off > 0; off >>= 1)
                v += __shfl_xor_sync(0xffffffffu, v, off, 32);
            if (lane == 0) g_CS[b][which] = v;
        }

        float4 acc = make_float4(0.f, 0.f, 0.f, 0.f);
        float4 buf[BATCH];
        const int ms0 = fs * (MSPLIT / 4);
#pragma unroll
        for (int mm = 0; mm < MSPLIT / 4; mm += BATCH) {
#pragma unroll
            for (int i = 0; i < BATCH; ++i)
                buf[i] = __ldcg(&((const float4*)g_part[b][ms0 + mm + i][comp])[col]);
#pragma unroll
            for (int i = 0; i < BATCH; ++i) {
                acc.x += buf[i].x; acc.y += buf[i].y;
                acc.z += buf[i].z; acc.w += buf[i].w;
            }
        }
        if (fs != 0) sred[fs][t & 63] = acc;
        __syncthreads();
        if (t < 64) {
#pragma unroll
            for (int i = 1; i < 4; ++i) {
                float4 v = sred[i][t];
                acc.x += v.x; acc.y += v.y; acc.z += v.z; acc.w += v.w;
            }
            ((float4*)g_H[b][comp])[col] = acc;
        }
    }

    grid_barrier(1, nb);

    // ================= Phase C: output for this block's own 32 rows ========
    const float a    = fminf(fmaxf(alpha_p[0], 0.f), 1.f);
    const float beta = 1.f - a;

    if (t < MCHUNK) {
        float C = __ldcg(&g_CS[b][0]);
        float S = __ldcg(&g_CS[b][1]);
        float den = fmaxf(0.5f * ((float)NN + fmaf(smc[t], C, sms[t] * S)), EPSV);
        scf[t] = a * 0.5f / den;
    }
    __syncthreads();

    const float4 H0 = __ldcg(&((const float4*)g_H[b][0])[t]);
    const float4 Hc = __ldcg(&((const float4*)g_H[b][1])[t]);
    const float4 Hs = __ldcg(&((const float4*)g_H[b][2])[t]);

    float4* ov = (float4*)(out + ((size_t)b * NN + m0) * DDIM) + t;

    float4 buf[BATCH];
#pragma unroll
    for (int rr = 0; rr < MCHUNK; rr += BATCH) {
#pragma unroll
        for (int i = 0; i < BATCH; ++i)
            buf[i] = hp[(size_t)(rr + i) * (DDIM / 4)];   // L1/L2-hot re-read
#pragma unroll
        for (int i = 0; i < BATCH; ++i) {
            int r = rr + i;
            float cn = smc[r], sn = sms[r], cf = scf[r];
            float4 h = buf[i];
            float4 o;
            o.x = fmaf(cf, fmaf(sn, Hs.x, fmaf(cn, Hc.x, H0.x)), beta * h.x);
            o.y = fmaf(cf, fmaf(sn, Hs.y, fmaf(cn, Hc.y, H0.y)), beta * h.y);
            o.z = fmaf(cf, fmaf(sn, Hs.z, fmaf(cn, Hc.z, H0.z)), beta * h.z);
            o.w = fmaf(cf, fmaf(sn, Hs.w, fmaf(cn, Hc.w, H0.w)), beta * h.w);
            __stcs(&ov[(size_t)r * (DDIM / 4)], o);       // evict-first stores
        }
    }
}

// ---------------------------------------------------------------------------
// Launch — single fused kernel.
// ---------------------------------------------------------------------------
extern "C" void kernel_launch(void* const* d_in, const int* in_sizes, int n_in,
                              void* d_out, int out_size) {
    const float* hidden = (const float*)d_in[0];
    const float* phases = (const float*)d_in[1];
    const float* alpha  = (const float*)d_in[2];
    float* out = (float*)d_out;

    const int B = in_sizes[1] / NN;

    kernel_fused<<<dim3(MSPLIT, B), 256>>>(hidden, phases, alpha, out);
}

// round 16
// speedup vs baseline: 2.0382x; 2.0382x over previous
#include <cuda_runtime.h>
#include <cstdint>
#include <math.h>

#define BMAX   4
#define NN     4096
#define DDIM   1024
#define MSPLIT 128
#define MCHUNK (NN / MSPLIT)     // 32
#define EPSV   1e-6f
#define ROWS_PER_BLOCK 32
#define BATCH  8
#define STAGE_ROWS 2
#define NSTAGES 5                // 5-deep cp.async pipeline (40KB smem)
#define OITER   (ROWS_PER_BLOCK / STAGE_ROWS)  // 16

// Scratch (device globals: no allocation allowed)
__device__ float g_part[BMAX][MSPLIT][3][DDIM]; // partial H0/Hc/Hs (6 MB)
__device__ float g_csp[BMAX][MSPLIT][2];        // partial sum cos / sum sin
__device__ float g_H[BMAX][3][DDIM];            // reduced H0/Hc/Hs
__device__ float g_CS[BMAX][2];                 // final sum cos, sum sin

// ---- cp.async helpers (per-thread groups; no block sync needed) -----------
__device__ __forceinline__ void cp_async16(void* smem_dst, const void* gmem_src) {
    unsigned int s = (unsigned int)__cvta_generic_to_shared(smem_dst);
    asm volatile("cp.async.cg.shared.global [%0], [%1], 16;\n" :: "r"(s), "l"(gmem_src));
}
#define CP_COMMIT() asm volatile("cp.async.commit_group;\n" ::: "memory")
#define CP_WAIT4()  asm volatile("cp.async.wait_group 4;\n" ::: "memory")

// ---------------------------------------------------------------------------
// Kernel 1 (R7-best): partial H0/Hc/Hs, register-batched loads (MLP=8).
// grid = (MSPLIT, B) = 512 blocks, 256 threads, thread owns 4 consecutive d.
// ---------------------------------------------------------------------------
__global__ void __launch_bounds__(256, 4)
kernel_part(const float* __restrict__ hidden,
            const float* __restrict__ phases) {
    __shared__ float smc[MCHUNK], sms[MCHUNK];
    const int b  = blockIdx.y;
    const int ms = blockIdx.x;
    const int m0 = ms * MCHUNK;
    const int t  = threadIdx.x;

    if (t < MCHUNK) {
        float p = phases[b * NN + m0 + t];
        float s, c;
        sincosf(p, &s, &c);
        smc[t] = c;
        sms[t] = s;
        float rc = c, rs = s;
#pragma unroll
        for (int off = 16; off > 0; off >>= 1) {
            rc += __shfl_xor_sync(0xffffffffu, rc, off);
            rs += __shfl_xor_sync(0xffffffffu, rs, off);
        }
        if (t == 0) { g_csp[b][ms][0] = rc; g_csp[b][ms][1] = rs; }
    }
    __syncthreads();

    const float4* hp = (const float4*)(hidden + ((size_t)b * NN + m0) * DDIM) + t;
    float4 a0 = make_float4(0.f, 0.f, 0.f, 0.f);
    float4 ac = a0, as = a0;

    float4 buf[BATCH];
#pragma unroll
    for (int mm = 0; mm < MCHUNK; mm += BATCH) {
#pragma unroll
        for (int i = 0; i < BATCH; ++i)
            buf[i] = hp[(size_t)(mm + i) * (DDIM / 4)];
#pragma unroll
        for (int i = 0; i < BATCH; ++i) {
            float4 h = buf[i];
            float c = smc[mm + i], s = sms[mm + i];
            a0.x += h.x;               a0.y += h.y;
            a0.z += h.z;               a0.w += h.w;
            ac.x = fmaf(c, h.x, ac.x); ac.y = fmaf(c, h.y, ac.y);
            ac.z = fmaf(c, h.z, ac.z); ac.w = fmaf(c, h.w, ac.w);
            as.x = fmaf(s, h.x, as.x); as.y = fmaf(s, h.y, as.y);
            as.z = fmaf(s, h.z, as.z); as.w = fmaf(s, h.w, as.w);
        }
    }
    __stcg(&((float4*)g_part[b][ms][0])[t], a0);   // bypass L1
    __stcg(&((float4*)g_part[b][ms][1])[t], ac);
    __stcg(&((float4*)g_part[b][ms][2])[t], as);
}

// ---------------------------------------------------------------------------
// Kernel 2: fold MSPLIT partials -> g_H with a 4-way split fold.
// grid = (12, B), 256 threads. Block: comp = bx>>2, d-quarter = bx&3 (64 f4).
// ---------------------------------------------------------------------------
__global__ void __launch_bounds__(256)
kernel_reduce() {
    __shared__ float4 sred[4][64];
    const int comp = blockIdx.x >> 2;
    const int q    = blockIdx.x & 3;
    const int b    = blockIdx.y;
    const int t    = threadIdx.x;
    const int col  = q * 64 + (t & 63);
    const int fs   = t >> 6;                  // 0..3

    if (blockIdx.x == 0 && t < 64) {
        int which = t >> 5;
        int lane  = t & 31;
        float v = 0.f;
#pragma unroll
        for (int i = 0; i < MSPLIT / 32; ++i)
            v += g_csp[b][lane + i * 32][which];
#pragma unroll
        for (int off = 16; off > 0; off >>= 1)
            v += __shfl_xor_sync(0xffffffffu, v, off, 32);
        if (lane == 0) g_CS[b][which] = v;
    }

    float4 acc = make_float4(0.f, 0.f, 0.f, 0.f);
    float4 buf[8];
    const int ms0 = fs * (MSPLIT / 4);
#pragma unroll
    for (int mm = 0; mm < MSPLIT / 4; mm += 8) {
#pragma unroll
        for (int i = 0; i < 8; ++i)
            buf[i] = ((const float4*)g_part[b][ms0 + mm + i][comp])[col];
#pragma unroll
        for (int i = 0; i < 8; ++i) {
            acc.x += buf[i].x; acc.y += buf[i].y;
            acc.z += buf[i].z; acc.w += buf[i].w;
        }
    }
    if (fs != 0) sred[fs][t & 63] = acc;
    __syncthreads();
    if (t < 64) {
#pragma unroll
        for (int i = 1; i < 4; ++i) {
            float4 v = sred[i][t];
            acc.x += v.x; acc.y += v.y; acc.z += v.z; acc.w += v.w;
        }
        ((float4*)g_H[b][comp])[col] = acc;
    }
}

// ---------------------------------------------------------------------------
// Kernel 3 (R12-best): output pass — 5-stage cp.async pipeline, FMA,
// evict-first stores. grid = (NN/32, B) = 512 blocks (single wave), 256 thr.
// ---------------------------------------------------------------------------
__global__ void __launch_bounds__(256)
kernel_out(const float* __restrict__ hidden,
           const float* __restrict__ phases,
           const float* __restrict__ alpha_p,
           float* __restrict__ out) {
    __shared__ float4 sbuf[NSTAGES][STAGE_ROWS][256];
    __shared__ float scn[ROWS_PER_BLOCK], ssn[ROWS_PER_BLOCK], scf[ROWS_PER_BLOCK];
    const int b  = blockIdx.y;
    const int n0 = blockIdx.x * ROWS_PER_BLOCK;
    const int t  = threadIdx.x;

    const float a    = fminf(fmaxf(alpha_p[0], 0.f), 1.f);
    const float beta = 1.f - a;

    if (t < ROWS_PER_BLOCK) {
        float p = phases[b * NN + n0 + t];
        float sn, cn;
        sincosf(p, &sn, &cn);
        float C = g_CS[b][0], S = g_CS[b][1];
        float den = fmaxf(0.5f * ((float)NN + fmaf(cn, C, sn * S)), EPSV);
        scn[t] = cn;
        ssn[t] = sn;
        scf[t] = a * 0.5f / den;
    }
    __syncthreads();

    const float4 H0 = ((const float4*)g_H[b][0])[t];
    const float4 Hc = ((const float4*)g_H[b][1])[t];
    const float4 Hs = ((const float4*)g_H[b][2])[t];

    const float4* hv = (const float4*)(hidden + ((size_t)b * NN + n0) * DDIM) + t;
    float4*       ov = (float4*)(out + ((size_t)b * NN + n0) * DDIM) + t;

    // prologue: stages 0..NSTAGES-2
#pragma unroll
    for (int s = 0; s < NSTAGES - 1; ++s) {
#pragma unroll
        for (int r = 0; r < STAGE_ROWS; ++r)
            cp_async16(&sbuf[s][r][t], hv + (size_t)(s * STAGE_ROWS + r) * (DDIM / 4));
        CP_COMMIT();
    }

#pragma unroll
    for (int it = 0; it < OITER; ++it) {
        const int nxt = it + NSTAGES - 1;
        if (nxt < OITER) {
#pragma unroll
            for (int r = 0; r < STAGE_ROWS; ++r)
                cp_async16(&sbuf[nxt % NSTAGES][r][t],
                           hv + (size_t)(nxt * STAGE_ROWS + r) * (DDIM / 4));
        }
        CP_COMMIT();
        CP_WAIT4();
#pragma unroll
        for (int r = 0; r < STAGE_ROWS; ++r) {
            int row = it * STAGE_ROWS + r;
            float cn = scn[row], sn = ssn[row], cf = scf[row];
            float4 h = sbuf[it % NSTAGES][r][t];
            float4 o;
            o.x = fmaf(cf, fmaf(sn, Hs.x, fmaf(cn, Hc.x, H0.x)), beta * h.x);
            o.y = fmaf(cf, fmaf(sn, Hs.y, fmaf(cn, Hc.y, H0.y)), beta * h.y);
            o.z = fmaf(cf, fmaf(sn, Hs.z, fmaf(cn, Hc.z, H0.z)), beta * h.z);
            o.w = fmaf(cf, fmaf(sn, Hs.w, fmaf(cn, Hc.w, H0.w)), beta * h.w);
            __stcs(&ov[(size_t)row * (DDIM / 4)], o);  // evict-first
        }
    }
}

// ---------------------------------------------------------------------------
// Launch — exactly 3 kernels.
// ---------------------------------------------------------------------------
extern "C" void kernel_launch(void* const* d_in, const int* in_sizes, int n_in,
                              void* d_out, int out_size) {
    const float* hidden = (const float*)d_in[0];
    const float* phases = (const float*)d_in[1];
    const float* alpha  = (const float*)d_in[2];
    float* out = (float*)d_out;

    const int B = in_sizes[1] / NN;

    kernel_part<<<dim3(MSPLIT, B), 256>>>(hidden, phases);
    kernel_reduce<<<dim3(12, B), 256>>>();
    kernel_out<<<dim3(NN / ROWS_PER_BLOCK, B), 256>>>(hidden, phases, alpha, out);
}